// round 1
// baseline (speedup 1.0000x reference)
#include <cuda_runtime.h>
#include <math.h>

#define NN   100000
#define NE   1600000
#define DIM  256
#define DOUT 40

// ---------------- scratch (static device globals; no runtime alloc) ----------
__device__ int   g_deg[NN];
__device__ int   g_cursor[NN];
__device__ int   g_rowptr[NN + 1];
__device__ int   g_col[NE];
__device__ float g_invdeg[NN];
__device__ float g_mean[(size_t)NN * DIM];
__device__ float g_h0[(size_t)NN * DIM];
__device__ float g_h1[(size_t)NN * DIM];

// ---------------- CSR build --------------------------------------------------
__global__ void zero_deg_k() {
    int i = blockIdx.x * blockDim.x + threadIdx.x;
    if (i < NN) g_deg[i] = 0;
}

__global__ void count_deg_k(const int* __restrict__ dst) {
    int e = blockIdx.x * blockDim.x + threadIdx.x;
    if (e < NE) atomicAdd(&g_deg[dst[e]], 1);
}

// single-block exclusive scan over g_deg -> g_rowptr / g_cursor, plus inv_deg
__global__ void scan_k() {
    __shared__ int warpsum[32];
    __shared__ int carry_s;
    int tid = threadIdx.x, lane = tid & 31, wid = tid >> 5;
    if (tid == 0) carry_s = 0;
    __syncthreads();
    for (int base = 0; base < NN; base += 1024) {
        int i = base + tid;
        int v = (i < NN) ? g_deg[i] : 0;
        int x = v;
        #pragma unroll
        for (int off = 1; off < 32; off <<= 1) {
            int t = __shfl_up_sync(0xffffffffu, x, off);
            if (lane >= off) x += t;
        }
        if (lane == 31) warpsum[wid] = x;
        __syncthreads();
        if (wid == 0) {
            int w = warpsum[lane];
            #pragma unroll
            for (int off = 1; off < 32; off <<= 1) {
                int t = __shfl_up_sync(0xffffffffu, w, off);
                if (lane >= off) w += t;
            }
            warpsum[lane] = w;
        }
        __syncthreads();
        int incl  = x + ((wid > 0) ? warpsum[wid - 1] : 0);
        int carry = carry_s;
        if (i < NN) {
            int excl = carry + incl - v;
            g_rowptr[i] = excl;
            g_cursor[i] = excl;
            g_invdeg[i] = 1.0f / (float)((v > 1) ? v : 1);
        }
        __syncthreads();
        if (tid == 1023) carry_s = carry + warpsum[31];
        __syncthreads();
    }
    if (threadIdx.x == 0) g_rowptr[NN] = carry_s;
}

__global__ void fill_csr_k(const int* __restrict__ src, const int* __restrict__ dst) {
    int e = blockIdx.x * blockDim.x + threadIdx.x;
    if (e < NE) {
        int d = dst[e];
        int p = atomicAdd(&g_cursor[d], 1);
        g_col[p] = src[e];
    }
}

// ---------------- aggregation: mean over in-neighbors -> g_mean --------------
// one warp per node; each lane owns 8 floats (2 x float4) of the 256-dim row
__global__ void aggregate_k(const float* __restrict__ h) {
    int node = (int)((blockIdx.x * blockDim.x + threadIdx.x) >> 5);
    if (node >= NN) return;
    int lane = threadIdx.x & 31;
    int beg = g_rowptr[node], end = g_rowptr[node + 1];
    float4 a0 = make_float4(0.f, 0.f, 0.f, 0.f);
    float4 a1 = make_float4(0.f, 0.f, 0.f, 0.f);
    for (int e = beg; e < end; ++e) {
        int s = g_col[e];
        const float4* r = reinterpret_cast<const float4*>(h + (size_t)s * DIM);
        float4 v0 = __ldg(&r[lane]);
        float4 v1 = __ldg(&r[lane + 32]);
        a0.x += v0.x; a0.y += v0.y; a0.z += v0.z; a0.w += v0.w;
        a1.x += v1.x; a1.y += v1.y; a1.z += v1.z; a1.w += v1.w;
    }
    float inv = g_invdeg[node];
    float4* o = reinterpret_cast<float4*>(g_mean + (size_t)node * DIM);
    o[lane]      = make_float4(a0.x * inv, a0.y * inv, a0.z * inv, a0.w * inv);
    o[lane + 32] = make_float4(a1.x * inv, a1.y * inv, a1.z * inv, a1.w * inv);
}

// ---------------- fused dual GEMM: C = A@Wl + B@Wr + bias (+ReLU) ------------
// BM=BN=64, BK=16, 256 threads, 4x4 per-thread register tile
template<bool RELU>
__global__ __launch_bounds__(256) void gemm2_k(
    const float* __restrict__ A,  const float* __restrict__ Bm,
    const float* __restrict__ Wl, const float* __restrict__ Wr,
    const float* __restrict__ bias, float* __restrict__ C, int Nout)
{
    const int BM = 64, BN = 64, BK = 16;
    __shared__ float As[BK][BM];
    __shared__ float Ws[BK][BN];
    int tid = threadIdx.x;
    int tx = tid & 15, ty = tid >> 4;
    int i0 = blockIdx.x * BM, j0 = blockIdx.y * BN;
    int arow = tid >> 2, acol = (tid & 3) << 2;   // A tile: 64 rows x 16 k
    int wk   = tid >> 4, wn   = (tid & 15) << 2;  // W tile: 16 k x 64 n

    float acc[4][4];
    #pragma unroll
    for (int r = 0; r < 4; ++r)
        #pragma unroll
        for (int c = 0; c < 4; ++c) acc[r][c] = 0.f;

    #pragma unroll
    for (int phase = 0; phase < 2; ++phase) {
        const float* Ap = phase ? Bm : A;
        const float* Wp = phase ? Wr : Wl;
        for (int k0 = 0; k0 < DIM; k0 += BK) {
            float4 av = make_float4(0.f, 0.f, 0.f, 0.f);
            int gi = i0 + arow;
            if (gi < NN)
                av = *reinterpret_cast<const float4*>(Ap + (size_t)gi * DIM + k0 + acol);
            As[acol + 0][arow] = av.x;
            As[acol + 1][arow] = av.y;
            As[acol + 2][arow] = av.z;
            As[acol + 3][arow] = av.w;

            float4 wv = make_float4(0.f, 0.f, 0.f, 0.f);
            if (j0 + wn < Nout)
                wv = *reinterpret_cast<const float4*>(Wp + (size_t)(k0 + wk) * Nout + j0 + wn);
            *reinterpret_cast<float4*>(&Ws[wk][wn]) = wv;
            __syncthreads();

            #pragma unroll
            for (int k = 0; k < BK; ++k) {
                float4 a = *reinterpret_cast<const float4*>(&As[k][ty << 2]);
                float4 w = *reinterpret_cast<const float4*>(&Ws[k][tx << 2]);
                acc[0][0] += a.x * w.x; acc[0][1] += a.x * w.y; acc[0][2] += a.x * w.z; acc[0][3] += a.x * w.w;
                acc[1][0] += a.y * w.x; acc[1][1] += a.y * w.y; acc[1][2] += a.y * w.z; acc[1][3] += a.y * w.w;
                acc[2][0] += a.z * w.x; acc[2][1] += a.z * w.y; acc[2][2] += a.z * w.z; acc[2][3] += a.z * w.w;
                acc[3][0] += a.w * w.x; acc[3][1] += a.w * w.y; acc[3][2] += a.w * w.z; acc[3][3] += a.w * w.w;
            }
            __syncthreads();
        }
    }

    int j = j0 + (tx << 2);
    if (j < Nout) {
        float4 bv = *reinterpret_cast<const float4*>(bias + j);
        #pragma unroll
        for (int r = 0; r < 4; ++r) {
            int gi = i0 + (ty << 2) + r;
            if (gi < NN) {
                float4 v = make_float4(acc[r][0] + bv.x, acc[r][1] + bv.y,
                                       acc[r][2] + bv.z, acc[r][3] + bv.w);
                if (RELU) {
                    v.x = fmaxf(v.x, 0.f); v.y = fmaxf(v.y, 0.f);
                    v.z = fmaxf(v.z, 0.f); v.w = fmaxf(v.w, 0.f);
                }
                *reinterpret_cast<float4*>(C + (size_t)gi * Nout + j) = v;
            }
        }
    }
}

// ---------------- log_softmax over 40 cols, warp per row ---------------------
__global__ void logsoftmax_k(float* __restrict__ io) {
    int row = (int)((blockIdx.x * blockDim.x + threadIdx.x) >> 5);
    if (row >= NN) return;
    int lane = threadIdx.x & 31;
    float v0 = (lane < DOUT)      ? io[(size_t)row * DOUT + lane]      : -INFINITY;
    float v1 = (lane + 32 < DOUT) ? io[(size_t)row * DOUT + lane + 32] : -INFINITY;
    float m = fmaxf(v0, v1);
    #pragma unroll
    for (int off = 16; off > 0; off >>= 1)
        m = fmaxf(m, __shfl_xor_sync(0xffffffffu, m, off));
    float s = 0.f;
    if (lane < DOUT)      s += expf(v0 - m);
    if (lane + 32 < DOUT) s += expf(v1 - m);
    #pragma unroll
    for (int off = 16; off > 0; off >>= 1)
        s += __shfl_xor_sync(0xffffffffu, s, off);
    float ls = m + logf(s);
    if (lane < DOUT)      io[(size_t)row * DOUT + lane]      = v0 - ls;
    if (lane + 32 < DOUT) io[(size_t)row * DOUT + lane + 32] = v1 - ls;
}

// ---------------- launch -----------------------------------------------------
extern "C" void kernel_launch(void* const* d_in, const int* in_sizes, int n_in,
                              void* d_out, int out_size) {
    const float* x   = (const float*)d_in[0];
    const int*   ei  = (const int*)d_in[1];
    const int*   src = ei;
    const int*   dst = ei + NE;
    const float* Wl0 = (const float*)d_in[2];
    const float* Wr0 = (const float*)d_in[3];
    const float* b0  = (const float*)d_in[4];
    const float* Wl1 = (const float*)d_in[5];
    const float* Wr1 = (const float*)d_in[6];
    const float* b1  = (const float*)d_in[7];
    const float* Wl2 = (const float*)d_in[8];
    const float* Wr2 = (const float*)d_in[9];
    const float* b2  = (const float*)d_in[10];
    float* out = (float*)d_out;

    float *p_mean, *p_h0, *p_h1;
    cudaGetSymbolAddress((void**)&p_mean, g_mean);
    cudaGetSymbolAddress((void**)&p_h0, g_h0);
    cudaGetSymbolAddress((void**)&p_h1, g_h1);

    // CSR build (per call; edges are an input)
    zero_deg_k<<<(NN + 255) / 256, 256>>>();
    count_deg_k<<<(NE + 255) / 256, 256>>>(dst);
    scan_k<<<1, 1024>>>();
    fill_csr_k<<<(NE + 255) / 256, 256>>>(src, dst);

    dim3 g256((NN + 63) / 64, (DIM + 63) / 64);
    dim3 g40((NN + 63) / 64, 1);
    int aggBlocks = (NN + 7) / 8;  // 8 warps per 256-thread block

    // layer 0
    aggregate_k<<<aggBlocks, 256>>>(x);
    gemm2_k<true><<<g256, 256>>>(p_mean, x, Wl0, Wr0, b0, p_h0, DIM);
    // layer 1
    aggregate_k<<<aggBlocks, 256>>>(p_h0);
    gemm2_k<true><<<g256, 256>>>(p_mean, p_h0, Wl1, Wr1, b1, p_h1, DIM);
    // layer 2 (writes logits straight into d_out)
    aggregate_k<<<aggBlocks, 256>>>(p_h1);
    gemm2_k<false><<<g40, 256>>>(p_mean, p_h1, Wl2, Wr2, b2, out, DOUT);
    // log_softmax in place
    logsoftmax_k<<<aggBlocks, 256>>>(out);
}

// round 2
// speedup vs baseline: 1.3253x; 1.3253x over previous
#include <cuda_runtime.h>
#include <math.h>

#define NN   100000
#define NE   1600000
#define DIM  256
#define DOUT 40

// ---------------- scratch (static device globals; no runtime alloc) ----------
__device__ int   g_deg[NN];
__device__ int   g_cursor[NN];
__device__ int   g_rowptr[NN + 1];
__device__ int   g_col[NE];
__device__ float g_invdeg[NN];
__device__ float g_mean[(size_t)NN * DIM];
__device__ float g_h0[(size_t)NN * DIM];
__device__ float g_h1[(size_t)NN * DIM];
__device__ float g_z[(size_t)NN * 80];      // layer-2 projected features [yl(40) | yr(40)]
__device__ float g_W2[(size_t)DIM * 80];    // packed [Wl2 | Wr2]
__device__ float g_bzero[128];              // stays zero (never written)

// ---------------- CSR build --------------------------------------------------
__global__ void zero_deg_k() {
    int i = blockIdx.x * blockDim.x + threadIdx.x;
    if (i < NN) g_deg[i] = 0;
}

__global__ void count_deg_k(const int* __restrict__ dst) {
    int e = blockIdx.x * blockDim.x + threadIdx.x;
    if (e < NE) atomicAdd(&g_deg[dst[e]], 1);
}

// single-block exclusive scan over g_deg -> g_rowptr / g_cursor, plus inv_deg
__global__ void scan_k() {
    __shared__ int warpsum[32];
    __shared__ int carry_s;
    int tid = threadIdx.x, lane = tid & 31, wid = tid >> 5;
    if (tid == 0) carry_s = 0;
    __syncthreads();
    for (int base = 0; base < NN; base += 1024) {
        int i = base + tid;
        int v = (i < NN) ? g_deg[i] : 0;
        int x = v;
        #pragma unroll
        for (int off = 1; off < 32; off <<= 1) {
            int t = __shfl_up_sync(0xffffffffu, x, off);
            if (lane >= off) x += t;
        }
        if (lane == 31) warpsum[wid] = x;
        __syncthreads();
        if (wid == 0) {
            int w = warpsum[lane];
            #pragma unroll
            for (int off = 1; off < 32; off <<= 1) {
                int t = __shfl_up_sync(0xffffffffu, w, off);
                if (lane >= off) w += t;
            }
            warpsum[lane] = w;
        }
        __syncthreads();
        int incl  = x + ((wid > 0) ? warpsum[wid - 1] : 0);
        int carry = carry_s;
        if (i < NN) {
            int excl = carry + incl - v;
            g_rowptr[i] = excl;
            g_cursor[i] = excl;
            g_invdeg[i] = 1.0f / (float)((v > 1) ? v : 1);
        }
        __syncthreads();
        if (tid == 1023) carry_s = carry + warpsum[31];
        __syncthreads();
    }
    if (threadIdx.x == 0) g_rowptr[NN] = carry_s;
}

__global__ void fill_csr_k(const int* __restrict__ src, const int* __restrict__ dst) {
    int e = blockIdx.x * blockDim.x + threadIdx.x;
    if (e < NE) {
        int d = dst[e];
        int p = atomicAdd(&g_cursor[d], 1);
        g_col[p] = src[e];
    }
}

// ---------------- aggregation: mean over in-neighbors (256-dim) --------------
__global__ void aggregate_k(const float* __restrict__ h) {
    int node = (int)((blockIdx.x * blockDim.x + threadIdx.x) >> 5);
    if (node >= NN) return;
    int lane = threadIdx.x & 31;
    int beg = g_rowptr[node], end = g_rowptr[node + 1];
    float4 a0 = make_float4(0.f, 0.f, 0.f, 0.f);
    float4 a1 = make_float4(0.f, 0.f, 0.f, 0.f);
    for (int e = beg; e < end; ++e) {
        int s = g_col[e];
        const float4* r = reinterpret_cast<const float4*>(h + (size_t)s * DIM);
        float4 v0 = __ldg(&r[lane]);
        float4 v1 = __ldg(&r[lane + 32]);
        a0.x += v0.x; a0.y += v0.y; a0.z += v0.z; a0.w += v0.w;
        a1.x += v1.x; a1.y += v1.y; a1.z += v1.z; a1.w += v1.w;
    }
    float inv = g_invdeg[node];
    float4* o = reinterpret_cast<float4*>(g_mean + (size_t)node * DIM);
    o[lane]      = make_float4(a0.x * inv, a0.y * inv, a0.z * inv, a0.w * inv);
    o[lane + 32] = make_float4(a1.x * inv, a1.y * inv, a1.z * inv, a1.w * inv);
}

// ---------------- 128x128x8 double-buffered SGEMM ----------------------------
// C[i][j] = sum_p  Ap[i][:] @ Wp[:][j]   (+ bias, optional ReLU)
// A row-major (stride DIM), W row-major (stride Nout). 256 threads, 8x8/thread.
template<bool RELU>
__global__ __launch_bounds__(256) void gemm128_k(
    const float* __restrict__ A0, const float* __restrict__ A1,
    const float* __restrict__ W0, const float* __restrict__ W1,
    const float* __restrict__ bias, float* __restrict__ C,
    int Nout, int nphase)
{
    __shared__ float As[2][8][128];
    __shared__ float Ws[2][8][128];
    int tid = threadIdx.x;
    int tx = tid & 15, ty = tid >> 4;
    int i0 = blockIdx.x * 128, j0 = blockIdx.y * 128;
    int arow = tid >> 1, acol = (tid & 1) << 2;  // A tile: 128 rows x 8 k
    int wk   = tid >> 5, wn   = (tid & 31) << 2; // W tile: 8 k x 128 n

    float acc[8][8];
    #pragma unroll
    for (int r = 0; r < 8; ++r)
        #pragma unroll
        for (int c = 0; c < 8; ++c) acc[r][c] = 0.f;

    const int gi = i0 + arow;
    const bool a_ok = (gi < NN);
    const bool w_ok = (j0 + wn < Nout);

    for (int p = 0; p < nphase; ++p) {
        const float* Ap = p ? A1 : A0;
        const float* Wp = p ? W1 : W0;

        // prologue: tile 0 -> buf 0
        float4 ra = make_float4(0.f, 0.f, 0.f, 0.f);
        float4 rw = make_float4(0.f, 0.f, 0.f, 0.f);
        if (a_ok) ra = *reinterpret_cast<const float4*>(Ap + (size_t)gi * DIM + acol);
        if (w_ok) rw = *reinterpret_cast<const float4*>(Wp + (size_t)wk * Nout + j0 + wn);
        As[0][acol + 0][arow] = ra.x;
        As[0][acol + 1][arow] = ra.y;
        As[0][acol + 2][arow] = ra.z;
        As[0][acol + 3][arow] = ra.w;
        *reinterpret_cast<float4*>(&Ws[0][wk][wn]) = rw;
        __syncthreads();

        int buf = 0;
        for (int k0 = 8; k0 < DIM; k0 += 8) {
            // prefetch next tile (global)
            float4 na = make_float4(0.f, 0.f, 0.f, 0.f);
            float4 nw = make_float4(0.f, 0.f, 0.f, 0.f);
            if (a_ok) na = *reinterpret_cast<const float4*>(Ap + (size_t)gi * DIM + k0 + acol);
            if (w_ok) nw = *reinterpret_cast<const float4*>(Wp + (size_t)(k0 + wk) * Nout + j0 + wn);

            // compute current buffer
            #pragma unroll
            for (int k = 0; k < 8; ++k) {
                float4 a0v = *reinterpret_cast<const float4*>(&As[buf][k][ty << 2]);
                float4 a1v = *reinterpret_cast<const float4*>(&As[buf][k][(ty << 2) + 64]);
                float4 b0v = *reinterpret_cast<const float4*>(&Ws[buf][k][tx << 2]);
                float4 b1v = *reinterpret_cast<const float4*>(&Ws[buf][k][(tx << 2) + 64]);
                float am[8] = {a0v.x, a0v.y, a0v.z, a0v.w, a1v.x, a1v.y, a1v.z, a1v.w};
                float bn[8] = {b0v.x, b0v.y, b0v.z, b0v.w, b1v.x, b1v.y, b1v.z, b1v.w};
                #pragma unroll
                for (int r = 0; r < 8; ++r)
                    #pragma unroll
                    for (int c = 0; c < 8; ++c)
                        acc[r][c] += am[r] * bn[c];
            }

            // stage next tile
            int nb = buf ^ 1;
            As[nb][acol + 0][arow] = na.x;
            As[nb][acol + 1][arow] = na.y;
            As[nb][acol + 2][arow] = na.z;
            As[nb][acol + 3][arow] = na.w;
            *reinterpret_cast<float4*>(&Ws[nb][wk][wn]) = nw;
            __syncthreads();
            buf = nb;
        }

        // final tile of this phase
        #pragma unroll
        for (int k = 0; k < 8; ++k) {
            float4 a0v = *reinterpret_cast<const float4*>(&As[buf][k][ty << 2]);
            float4 a1v = *reinterpret_cast<const float4*>(&As[buf][k][(ty << 2) + 64]);
            float4 b0v = *reinterpret_cast<const float4*>(&Ws[buf][k][tx << 2]);
            float4 b1v = *reinterpret_cast<const float4*>(&Ws[buf][k][(tx << 2) + 64]);
            float am[8] = {a0v.x, a0v.y, a0v.z, a0v.w, a1v.x, a1v.y, a1v.z, a1v.w};
            float bn[8] = {b0v.x, b0v.y, b0v.z, b0v.w, b1v.x, b1v.y, b1v.z, b1v.w};
            #pragma unroll
            for (int r = 0; r < 8; ++r)
                #pragma unroll
                for (int c = 0; c < 8; ++c)
                    acc[r][c] += am[r] * bn[c];
        }
        __syncthreads();   // protect buffers before next phase's prologue
    }

    // epilogue
    #pragma unroll
    for (int rh = 0; rh < 2; ++rh) {
        #pragma unroll
        for (int r = 0; r < 4; ++r) {
            int grow = i0 + (ty << 2) + r + rh * 64;
            if (grow >= NN) continue;
            #pragma unroll
            for (int ch = 0; ch < 2; ++ch) {
                int gcol = j0 + (tx << 2) + ch * 64;
                if (gcol >= Nout) continue;
                float4 bv = *reinterpret_cast<const float4*>(bias + gcol);
                float4 v = make_float4(acc[r + rh * 4][ch * 4 + 0] + bv.x,
                                       acc[r + rh * 4][ch * 4 + 1] + bv.y,
                                       acc[r + rh * 4][ch * 4 + 2] + bv.z,
                                       acc[r + rh * 4][ch * 4 + 3] + bv.w);
                if (RELU) {
                    v.x = fmaxf(v.x, 0.f); v.y = fmaxf(v.y, 0.f);
                    v.z = fmaxf(v.z, 0.f); v.w = fmaxf(v.w, 0.f);
                }
                *reinterpret_cast<float4*>(C + (size_t)grow * Nout + gcol) = v;
            }
        }
    }
}

// ---------------- pack [Wl2 | Wr2] into g_W2 (256 x 80) ----------------------
__global__ void pack_w2_k(const float* __restrict__ Wl2, const float* __restrict__ Wr2) {
    int i = blockIdx.x * blockDim.x + threadIdx.x;
    if (i < DIM * DOUT) {
        int k = i / DOUT, n = i % DOUT;
        g_W2[(size_t)k * 80 + n]      = Wl2[i];
        g_W2[(size_t)k * 80 + 40 + n] = Wr2[i];
    }
}

// ------- layer-2 tail: aggregate 40-dim + root + bias + log_softmax ----------
// z = [yl | yr] (NN x 80). out[i] = logsoftmax( mean_agg(yl)[i] + yr[i] + b2 )
__global__ void agg40_lsm_k(const float* __restrict__ b2, float* __restrict__ out) {
    int node = (int)((blockIdx.x * blockDim.x + threadIdx.x) >> 5);
    if (node >= NN) return;
    int lane = threadIdx.x & 31;
    int beg = g_rowptr[node], end = g_rowptr[node + 1];
    float s0 = 0.f, s1 = 0.f;
    for (int e = beg; e < end; ++e) {
        int s = g_col[e];
        const float* zr = g_z + (size_t)s * 80;
        s0 += __ldg(zr + lane);
        if (lane < 8) s1 += __ldg(zr + 32 + lane);
    }
    float inv = g_invdeg[node];
    const float* zn = g_z + (size_t)node * 80;
    float v0 = s0 * inv + zn[40 + lane] + b2[lane];
    float v1 = (lane < 8) ? (s1 * inv + zn[72 + lane] + b2[32 + lane]) : -INFINITY;
    float m = fmaxf(v0, v1);
    #pragma unroll
    for (int off = 16; off > 0; off >>= 1)
        m = fmaxf(m, __shfl_xor_sync(0xffffffffu, m, off));
    float s = expf(v0 - m) + ((lane < 8) ? expf(v1 - m) : 0.f);
    #pragma unroll
    for (int off = 16; off > 0; off >>= 1)
        s += __shfl_xor_sync(0xffffffffu, s, off);
    float ls = m + logf(s);
    out[(size_t)node * DOUT + lane] = v0 - ls;
    if (lane < 8) out[(size_t)node * DOUT + 32 + lane] = v1 - ls;
}

// ---------------- launch -----------------------------------------------------
extern "C" void kernel_launch(void* const* d_in, const int* in_sizes, int n_in,
                              void* d_out, int out_size) {
    const float* x   = (const float*)d_in[0];
    const int*   ei  = (const int*)d_in[1];
    const int*   src = ei;
    const int*   dst = ei + NE;
    const float* Wl0 = (const float*)d_in[2];
    const float* Wr0 = (const float*)d_in[3];
    const float* b0  = (const float*)d_in[4];
    const float* Wl1 = (const float*)d_in[5];
    const float* Wr1 = (const float*)d_in[6];
    const float* b1  = (const float*)d_in[7];
    const float* Wl2 = (const float*)d_in[8];
    const float* Wr2 = (const float*)d_in[9];
    const float* b2  = (const float*)d_in[10];
    float* out = (float*)d_out;

    float *p_mean, *p_h0, *p_h1, *p_z, *p_W2, *p_bz;
    cudaGetSymbolAddress((void**)&p_mean, g_mean);
    cudaGetSymbolAddress((void**)&p_h0, g_h0);
    cudaGetSymbolAddress((void**)&p_h1, g_h1);
    cudaGetSymbolAddress((void**)&p_z, g_z);
    cudaGetSymbolAddress((void**)&p_W2, g_W2);
    cudaGetSymbolAddress((void**)&p_bz, g_bzero);

    // CSR build
    zero_deg_k<<<(NN + 255) / 256, 256>>>();
    count_deg_k<<<(NE + 255) / 256, 256>>>(dst);
    scan_k<<<1, 1024>>>();
    fill_csr_k<<<(NE + 255) / 256, 256>>>(src, dst);
    pack_w2_k<<<(DIM * DOUT + 255) / 256, 256>>>(Wl2, Wr2);

    dim3 gmain((NN + 127) / 128, 2);   // Nout=256
    dim3 gz((NN + 127) / 128, 1);      // Nout=80
    int aggBlocks = (NN * 32 + 255) / 256;

    // layer 0
    aggregate_k<<<aggBlocks, 256>>>(x);
    gemm128_k<true><<<gmain, 256>>>(p_mean, x, Wl0, Wr0, b0, p_h0, DIM, 2);
    // layer 1
    aggregate_k<<<aggBlocks, 256>>>(p_h0);
    gemm128_k<true><<<gmain, 256>>>(p_mean, p_h0, Wl1, Wr1, b1, p_h1, DIM, 2);
    // layer 2: project first (linearity), then aggregate in 40-dim + softmax
    gemm128_k<false><<<gz, 256>>>(p_h1, nullptr, p_W2, nullptr, p_bz, p_z, 80, 1);
    agg40_lsm_k<<<aggBlocks, 256>>>(b2, out);
}

// round 3
// speedup vs baseline: 1.6372x; 1.2354x over previous
#include <cuda_runtime.h>
#include <math.h>

#define NN   100000
#define NE   1600000
#define DIM  256
#define DOUT 40

// ---------------- scratch (static device globals; no runtime alloc) ----------
__device__ int   g_deg[NN];
__device__ int   g_cursor[NN];
__device__ int   g_rowptr[NN + 1];
__device__ int   g_col[NE];
__device__ float g_invdeg[NN];
__device__ float g_mean[(size_t)NN * DIM];
__device__ float g_h0[(size_t)NN * DIM];
__device__ float g_h1[(size_t)NN * DIM];
__device__ float g_z[(size_t)NN * 80];      // layer-2 projected [yl(40) | yr(40)]
__device__ float g_W2[(size_t)DIM * 80];    // packed [Wl2 | Wr2]
__device__ float g_bzero[128];              // stays zero

// ---------------- CSR build --------------------------------------------------
__global__ void zero_deg_k() {
    int i = blockIdx.x * blockDim.x + threadIdx.x;
    if (i < NN) g_deg[i] = 0;
}

__global__ void count_deg_k(const int* __restrict__ dst) {
    int e = blockIdx.x * blockDim.x + threadIdx.x;
    if (e < NE) atomicAdd(&g_deg[dst[e]], 1);
}

__global__ void scan_k() {
    __shared__ int warpsum[32];
    __shared__ int carry_s;
    int tid = threadIdx.x, lane = tid & 31, wid = tid >> 5;
    if (tid == 0) carry_s = 0;
    __syncthreads();
    for (int base = 0; base < NN; base += 1024) {
        int i = base + tid;
        int v = (i < NN) ? g_deg[i] : 0;
        int x = v;
        #pragma unroll
        for (int off = 1; off < 32; off <<= 1) {
            int t = __shfl_up_sync(0xffffffffu, x, off);
            if (lane >= off) x += t;
        }
        if (lane == 31) warpsum[wid] = x;
        __syncthreads();
        if (wid == 0) {
            int w = warpsum[lane];
            #pragma unroll
            for (int off = 1; off < 32; off <<= 1) {
                int t = __shfl_up_sync(0xffffffffu, w, off);
                if (lane >= off) w += t;
            }
            warpsum[lane] = w;
        }
        __syncthreads();
        int incl  = x + ((wid > 0) ? warpsum[wid - 1] : 0);
        int carry = carry_s;
        if (i < NN) {
            int excl = carry + incl - v;
            g_rowptr[i] = excl;
            g_cursor[i] = excl;
            g_invdeg[i] = 1.0f / (float)((v > 1) ? v : 1);
        }
        __syncthreads();
        if (tid == 1023) carry_s = carry + warpsum[31];
        __syncthreads();
    }
    if (threadIdx.x == 0) g_rowptr[NN] = carry_s;
}

__global__ void fill_csr_k(const int* __restrict__ src, const int* __restrict__ dst) {
    int e = blockIdx.x * blockDim.x + threadIdx.x;
    if (e < NE) {
        int d = dst[e];
        int p = atomicAdd(&g_cursor[d], 1);
        g_col[p] = src[e];
    }
}

// ---------------- aggregation: mean over in-neighbors (256-dim) --------------
__global__ void aggregate_k(const float* __restrict__ h) {
    int node = (int)((blockIdx.x * blockDim.x + threadIdx.x) >> 5);
    if (node >= NN) return;
    int lane = threadIdx.x & 31;
    int beg = g_rowptr[node], end = g_rowptr[node + 1];
    float4 a0 = make_float4(0.f, 0.f, 0.f, 0.f);
    float4 a1 = make_float4(0.f, 0.f, 0.f, 0.f);
    for (int e = beg; e < end; ++e) {
        int s = g_col[e];
        const float4* r = reinterpret_cast<const float4*>(h + (size_t)s * DIM);
        float4 v0 = __ldg(&r[lane]);
        float4 v1 = __ldg(&r[lane + 32]);
        a0.x += v0.x; a0.y += v0.y; a0.z += v0.z; a0.w += v0.w;
        a1.x += v1.x; a1.y += v1.y; a1.z += v1.z; a1.w += v1.w;
    }
    float inv = g_invdeg[node];
    float4* o = reinterpret_cast<float4*>(g_mean + (size_t)node * DIM);
    o[lane]      = make_float4(a0.x * inv, a0.y * inv, a0.z * inv, a0.w * inv);
    o[lane + 32] = make_float4(a1.x * inv, a1.y * inv, a1.z * inv, a1.w * inv);
}

// ---------------- TF32 tensor-core GEMM (m16n8k8 mma.sync) -------------------
__device__ __forceinline__ float f2tf(float x) {
    unsigned r;
    asm("cvt.rna.tf32.f32 %0, %1;" : "=r"(r) : "f"(x));
    return __uint_as_float(r);
}

__device__ __forceinline__ void mma_tf32(float* d, const float* a, const float* b) {
    asm volatile(
        "mma.sync.aligned.m16n8k8.row.col.f32.tf32.tf32.f32 "
        "{%0,%1,%2,%3}, {%4,%5,%6,%7}, {%8,%9}, {%0,%1,%2,%3};"
        : "+f"(d[0]), "+f"(d[1]), "+f"(d[2]), "+f"(d[3])
        : "r"(__float_as_uint(a[0])), "r"(__float_as_uint(a[1])),
          "r"(__float_as_uint(a[2])), "r"(__float_as_uint(a[3])),
          "r"(__float_as_uint(b[0])), "r"(__float_as_uint(b[1])));
}

// C = A0@W0 (+ A1@W1) + bias, optional ReLU.
// A row-major stride DIM; W row-major stride Nout.
// BM=128 BN=128 BK=16, 256 threads = 8 warps (4x2), warp tile 32x64.
#define APAD 20   // row stride for [row][k] smem tiles — conflict-free for frag loads
template<bool RELU>
__global__ __launch_bounds__(256) void gemm_tf32_k(
    const float* __restrict__ A0, const float* __restrict__ A1,
    const float* __restrict__ W0, const float* __restrict__ W1,
    const float* __restrict__ bias, float* __restrict__ C,
    int Nout, int nphase)
{
    __shared__ float As[2][128 * APAD];   // [m-row][k]
    __shared__ float Ws[2][128 * APAD];   // [n-col][k]
    int tid = threadIdx.x;
    int lane = tid & 31, wid = tid >> 5;
    int wr = wid >> 1, wc = wid & 1;      // warp grid 4x2
    int i0 = blockIdx.x * 128, j0 = blockIdx.y * 128;

    // global->smem mapping
    int arow = tid >> 1, akb = (tid & 1) << 3;        // A: row, k-base(0/8)
    int wk   = tid >> 5, wn  = (tid & 31) << 2;       // W: k-row(+8), n-base
    int gi = i0 + arow; if (gi >= NN) gi = NN - 1;    // clamp (rows guarded at epilogue)
    const bool w_ok = (j0 + wn < Nout);

    float acc[2][8][4];
    #pragma unroll
    for (int mi = 0; mi < 2; ++mi)
        #pragma unroll
        for (int ni = 0; ni < 8; ++ni)
            #pragma unroll
            for (int q = 0; q < 4; ++q) acc[mi][ni][q] = 0.f;

    const int r4 = lane >> 2, c4 = lane & 3;          // fragment lane coords

    for (int p = 0; p < nphase; ++p) {
        const float* Ap = p ? A1 : A0;
        const float* Wp = p ? W1 : W0;

        // prologue: tile 0 -> buf 0
        {
            float4 ra0 = *reinterpret_cast<const float4*>(Ap + (size_t)gi * DIM + akb);
            float4 ra1 = *reinterpret_cast<const float4*>(Ap + (size_t)gi * DIM + akb + 4);
            float* as = &As[0][arow * APAD + akb];
            as[0] = f2tf(ra0.x); as[1] = f2tf(ra0.y); as[2] = f2tf(ra0.z); as[3] = f2tf(ra0.w);
            as[4] = f2tf(ra1.x); as[5] = f2tf(ra1.y); as[6] = f2tf(ra1.z); as[7] = f2tf(ra1.w);
            float4 rw0 = make_float4(0.f,0.f,0.f,0.f), rw1 = make_float4(0.f,0.f,0.f,0.f);
            if (w_ok) {
                rw0 = *reinterpret_cast<const float4*>(Wp + (size_t)wk * Nout + j0 + wn);
                rw1 = *reinterpret_cast<const float4*>(Wp + (size_t)(wk + 8) * Nout + j0 + wn);
            }
            #pragma unroll
            for (int q = 0; q < 4; ++q) {
                float v0 = (&rw0.x)[q], v1 = (&rw1.x)[q];
                Ws[0][(wn + q) * APAD + wk]     = f2tf(v0);
                Ws[0][(wn + q) * APAD + wk + 8] = f2tf(v1);
            }
        }
        __syncthreads();

        int buf = 0;
        for (int k0 = 16; k0 <= DIM; k0 += 16) {
            // prefetch next K-tile (unless last)
            float4 na0, na1, nw0, nw1;
            bool have_next = (k0 < DIM);
            if (have_next) {
                na0 = *reinterpret_cast<const float4*>(Ap + (size_t)gi * DIM + k0 + akb);
                na1 = *reinterpret_cast<const float4*>(Ap + (size_t)gi * DIM + k0 + akb + 4);
                nw0 = make_float4(0.f,0.f,0.f,0.f); nw1 = make_float4(0.f,0.f,0.f,0.f);
                if (w_ok) {
                    nw0 = *reinterpret_cast<const float4*>(Wp + (size_t)(k0 + wk) * Nout + j0 + wn);
                    nw1 = *reinterpret_cast<const float4*>(Wp + (size_t)(k0 + wk + 8) * Nout + j0 + wn);
                }
            }

            // compute on current buffer: 2 k-steps of 8
            #pragma unroll
            for (int kk = 0; kk < 2; ++kk) {
                int kb = kk * 8;
                float afr[2][4];
                #pragma unroll
                for (int mi = 0; mi < 2; ++mi) {
                    const float* base = &As[buf][(wr * 32 + mi * 16 + r4) * APAD + kb + c4];
                    afr[mi][0] = base[0];
                    afr[mi][1] = base[8 * APAD];
                    afr[mi][2] = base[4];
                    afr[mi][3] = base[8 * APAD + 4];
                }
                float bfr[8][2];
                #pragma unroll
                for (int ni = 0; ni < 8; ++ni) {
                    const float* base = &Ws[buf][(wc * 64 + ni * 8 + r4) * APAD + kb + c4];
                    bfr[ni][0] = base[0];
                    bfr[ni][1] = base[4];
                }
                #pragma unroll
                for (int mi = 0; mi < 2; ++mi)
                    #pragma unroll
                    for (int ni = 0; ni < 8; ++ni)
                        mma_tf32(acc[mi][ni], afr[mi], bfr[ni]);
            }

            if (have_next) {
                int nb = buf ^ 1;
                float* as = &As[nb][arow * APAD + akb];
                as[0] = f2tf(na0.x); as[1] = f2tf(na0.y); as[2] = f2tf(na0.z); as[3] = f2tf(na0.w);
                as[4] = f2tf(na1.x); as[5] = f2tf(na1.y); as[6] = f2tf(na1.z); as[7] = f2tf(na1.w);
                #pragma unroll
                for (int q = 0; q < 4; ++q) {
                    Ws[nb][(wn + q) * APAD + wk]     = f2tf((&nw0.x)[q]);
                    Ws[nb][(wn + q) * APAD + wk + 8] = f2tf((&nw1.x)[q]);
                }
                __syncthreads();
                buf = nb;
            }
        }
        __syncthreads();   // protect buffers before next phase prologue
    }

    // epilogue: c0,c1 at (row, col..col+1); c2,c3 at (row+8, ...)
    #pragma unroll
    for (int mi = 0; mi < 2; ++mi) {
        #pragma unroll
        for (int half = 0; half < 2; ++half) {
            int grow = i0 + wr * 32 + mi * 16 + r4 + half * 8;
            if (grow >= NN) continue;
            #pragma unroll
            for (int ni = 0; ni < 8; ++ni) {
                int gcol = j0 + wc * 64 + ni * 8 + c4 * 2;
                if (gcol >= Nout) continue;
                float b0v = bias[gcol], b1v = bias[gcol + 1];
                float v0 = acc[mi][ni][half * 2 + 0] + b0v;
                float v1 = acc[mi][ni][half * 2 + 1] + b1v;
                if (RELU) { v0 = fmaxf(v0, 0.f); v1 = fmaxf(v1, 0.f); }
                *reinterpret_cast<float2*>(C + (size_t)grow * Nout + gcol) =
                    make_float2(v0, v1);
            }
        }
    }
}

// ---------------- pack [Wl2 | Wr2] into g_W2 (256 x 80) ----------------------
__global__ void pack_w2_k(const float* __restrict__ Wl2, const float* __restrict__ Wr2) {
    int i = blockIdx.x * blockDim.x + threadIdx.x;
    if (i < DIM * DOUT) {
        int k = i / DOUT, n = i % DOUT;
        g_W2[(size_t)k * 80 + n]      = Wl2[i];
        g_W2[(size_t)k * 80 + 40 + n] = Wr2[i];
    }
}

// ------- layer-2 tail: aggregate 40-dim + root + bias + log_softmax ----------
__global__ void agg40_lsm_k(const float* __restrict__ b2, float* __restrict__ out) {
    int node = (int)((blockIdx.x * blockDim.x + threadIdx.x) >> 5);
    if (node >= NN) return;
    int lane = threadIdx.x & 31;
    int beg = g_rowptr[node], end = g_rowptr[node + 1];
    float s0 = 0.f, s1 = 0.f;
    for (int e = beg; e < end; ++e) {
        int s = g_col[e];
        const float* zr = g_z + (size_t)s * 80;
        s0 += __ldg(zr + lane);
        if (lane < 8) s1 += __ldg(zr + 32 + lane);
    }
    float inv = g_invdeg[node];
    const float* zn = g_z + (size_t)node * 80;
    float v0 = s0 * inv + zn[40 + lane] + b2[lane];
    float v1 = (lane < 8) ? (s1 * inv + zn[72 + lane] + b2[32 + lane]) : -INFINITY;
    float m = fmaxf(v0, v1);
    #pragma unroll
    for (int off = 16; off > 0; off >>= 1)
        m = fmaxf(m, __shfl_xor_sync(0xffffffffu, m, off));
    float s = expf(v0 - m) + ((lane < 8) ? expf(v1 - m) : 0.f);
    #pragma unroll
    for (int off = 16; off > 0; off >>= 1)
        s += __shfl_xor_sync(0xffffffffu, s, off);
    float ls = m + logf(s);
    out[(size_t)node * DOUT + lane] = v0 - ls;
    if (lane < 8) out[(size_t)node * DOUT + 32 + lane] = v1 - ls;
}

// ---------------- launch -----------------------------------------------------
extern "C" void kernel_launch(void* const* d_in, const int* in_sizes, int n_in,
                              void* d_out, int out_size) {
    const float* x   = (const float*)d_in[0];
    const int*   ei  = (const int*)d_in[1];
    const int*   src = ei;
    const int*   dst = ei + NE;
    const float* Wl0 = (const float*)d_in[2];
    const float* Wr0 = (const float*)d_in[3];
    const float* b0  = (const float*)d_in[4];
    const float* Wl1 = (const float*)d_in[5];
    const float* Wr1 = (const float*)d_in[6];
    const float* b1  = (const float*)d_in[7];
    const float* Wl2 = (const float*)d_in[8];
    const float* Wr2 = (const float*)d_in[9];
    const float* b2  = (const float*)d_in[10];
    float* out = (float*)d_out;

    float *p_mean, *p_h0, *p_h1, *p_z, *p_W2, *p_bz;
    cudaGetSymbolAddress((void**)&p_mean, g_mean);
    cudaGetSymbolAddress((void**)&p_h0, g_h0);
    cudaGetSymbolAddress((void**)&p_h1, g_h1);
    cudaGetSymbolAddress((void**)&p_z, g_z);
    cudaGetSymbolAddress((void**)&p_W2, g_W2);
    cudaGetSymbolAddress((void**)&p_bz, g_bzero);

    // CSR build
    zero_deg_k<<<(NN + 255) / 256, 256>>>();
    count_deg_k<<<(NE + 255) / 256, 256>>>(dst);
    scan_k<<<1, 1024>>>();
    fill_csr_k<<<(NE + 255) / 256, 256>>>(src, dst);
    pack_w2_k<<<(DIM * DOUT + 255) / 256, 256>>>(Wl2, Wr2);

    dim3 gmain((NN + 127) / 128, 2);   // Nout=256
    dim3 gz((NN + 127) / 128, 1);      // Nout=80
    int aggBlocks = (NN * 32 + 255) / 256;

    // layer 0
    aggregate_k<<<aggBlocks, 256>>>(x);
    gemm_tf32_k<true><<<gmain, 256>>>(p_mean, x, Wl0, Wr0, b0, p_h0, DIM, 2);
    // layer 1
    aggregate_k<<<aggBlocks, 256>>>(p_h0);
    gemm_tf32_k<true><<<gmain, 256>>>(p_mean, p_h0, Wl1, Wr1, b1, p_h1, DIM, 2);
    // layer 2: project first (linearity), then aggregate in 40-dim + softmax
    gemm_tf32_k<false><<<gz, 256>>>(p_h1, nullptr, p_W2, nullptr, p_bz, p_z, 80, 1);
    agg40_lsm_k<<<aggBlocks, 256>>>(b2, out);
}

// round 4
// speedup vs baseline: 3.1954x; 1.9517x over previous
#include <cuda_runtime.h>
#include <cuda_fp16.h>
#include <math.h>

#define NN   100000
#define NE   1600000
#define DIM  256
#define DOUT 40

// ---------------- scratch (static device globals; no runtime alloc) ----------
__device__ int    g_deg[NN];
__device__ int    g_cursor[NN];
__device__ int    g_rowptr[NN + 1];
__device__ int    g_col[NE];
__device__ float  g_invdeg[NN];
__device__ __half g_xh[(size_t)NN * DIM];
__device__ __half g_meanh[(size_t)NN * DIM];
__device__ __half g_h0h[(size_t)NN * DIM];
__device__ __half g_h1h[(size_t)NN * DIM];
__device__ float  g_z[(size_t)NN * 80];        // layer-2 projected [yl(40) | yr(40)]
__device__ __half g_Wl0h[DIM * DIM];           // transposed [n][k] fp16
__device__ __half g_Wr0h[DIM * DIM];
__device__ __half g_Wl1h[DIM * DIM];
__device__ __half g_Wr1h[DIM * DIM];
__device__ __half g_W2h[80 * DIM];             // [n(80)][k(256)]
__device__ float  g_bzero[128];                // stays zero

// ---------------- CSR build --------------------------------------------------
__global__ void zero_deg_k() {
    int i = blockIdx.x * blockDim.x + threadIdx.x;
    if (i < NN) g_deg[i] = 0;
}

__global__ void count_deg_k(const int* __restrict__ dst) {
    int e = blockIdx.x * blockDim.x + threadIdx.x;
    if (e < NE) atomicAdd(&g_deg[dst[e]], 1);
}

__global__ void scan_k() {
    __shared__ int warpsum[32];
    __shared__ int carry_s;
    int tid = threadIdx.x, lane = tid & 31, wid = tid >> 5;
    if (tid == 0) carry_s = 0;
    __syncthreads();
    for (int base = 0; base < NN; base += 1024) {
        int i = base + tid;
        int v = (i < NN) ? g_deg[i] : 0;
        int x = v;
        #pragma unroll
        for (int off = 1; off < 32; off <<= 1) {
            int t = __shfl_up_sync(0xffffffffu, x, off);
            if (lane >= off) x += t;
        }
        if (lane == 31) warpsum[wid] = x;
        __syncthreads();
        if (wid == 0) {
            int w = warpsum[lane];
            #pragma unroll
            for (int off = 1; off < 32; off <<= 1) {
                int t = __shfl_up_sync(0xffffffffu, w, off);
                if (lane >= off) w += t;
            }
            warpsum[lane] = w;
        }
        __syncthreads();
        int incl  = x + ((wid > 0) ? warpsum[wid - 1] : 0);
        int carry = carry_s;
        if (i < NN) {
            int excl = carry + incl - v;
            g_rowptr[i] = excl;
            g_cursor[i] = excl;
            g_invdeg[i] = 1.0f / (float)((v > 1) ? v : 1);
        }
        __syncthreads();
        if (tid == 1023) carry_s = carry + warpsum[31];
        __syncthreads();
    }
    if (threadIdx.x == 0) g_rowptr[NN] = carry_s;
}

__global__ void fill_csr_k(const int* __restrict__ src, const int* __restrict__ dst) {
    int e = blockIdx.x * blockDim.x + threadIdx.x;
    if (e < NE) {
        int d = dst[e];
        int p = atomicAdd(&g_cursor[d], 1);
        g_col[p] = src[e];
    }
}

// ---------------- conversions ------------------------------------------------
__global__ void conv_x_k(const float* __restrict__ x) {
    int i = blockIdx.x * blockDim.x + threadIdx.x;   // one float4 per thread
    int total = NN * DIM / 4;
    if (i < total) {
        float4 v = *reinterpret_cast<const float4*>(x + (size_t)i * 4);
        __half2 h0 = __floats2half2_rn(v.x, v.y);
        __half2 h1 = __floats2half2_rn(v.z, v.w);
        uint2 pk;
        pk.x = *reinterpret_cast<unsigned*>(&h0);
        pk.y = *reinterpret_cast<unsigned*>(&h1);
        *reinterpret_cast<uint2*>(g_xh + (size_t)i * 4) = pk;
    }
}

// out[n*K + k] = W[k*N + n], K = DIM fixed
__global__ void wpack_k(const float* __restrict__ W, __half* __restrict__ out, int N) {
    int i = blockIdx.x * blockDim.x + threadIdx.x;
    if (i < N * DIM) {
        int n = i / DIM, k = i % DIM;
        out[(size_t)n * DIM + k] = __float2half_rn(W[(size_t)k * N + n]);
    }
}

// ---------------- aggregation (fp16 gather, fp32 accumulate) -----------------
__device__ __forceinline__ void acc8(float* s, uint4 v) {
    __half2 a = *reinterpret_cast<__half2*>(&v.x);
    __half2 b = *reinterpret_cast<__half2*>(&v.y);
    __half2 c = *reinterpret_cast<__half2*>(&v.z);
    __half2 d = *reinterpret_cast<__half2*>(&v.w);
    float2 fa = __half22float2(a), fb = __half22float2(b);
    float2 fc = __half22float2(c), fd = __half22float2(d);
    s[0] += fa.x; s[1] += fa.y; s[2] += fb.x; s[3] += fb.y;
    s[4] += fc.x; s[5] += fc.y; s[6] += fd.x; s[7] += fd.y;
}

__global__ void aggregate_h_k(const __half* __restrict__ h) {
    int node = (int)((blockIdx.x * blockDim.x + threadIdx.x) >> 5);
    if (node >= NN) return;
    int lane = threadIdx.x & 31;
    int beg = g_rowptr[node], end = g_rowptr[node + 1];
    float s[8];
    #pragma unroll
    for (int q = 0; q < 8; ++q) s[q] = 0.f;
    int e = beg;
    for (; e + 1 < end; e += 2) {
        int s0 = g_col[e], s1 = g_col[e + 1];
        uint4 v0 = __ldg(reinterpret_cast<const uint4*>(h + (size_t)s0 * DIM) + lane);
        uint4 v1 = __ldg(reinterpret_cast<const uint4*>(h + (size_t)s1 * DIM) + lane);
        acc8(s, v0);
        acc8(s, v1);
    }
    if (e < end) {
        int s0 = g_col[e];
        uint4 v0 = __ldg(reinterpret_cast<const uint4*>(h + (size_t)s0 * DIM) + lane);
        acc8(s, v0);
    }
    float inv = g_invdeg[node];
    __half2 o0 = __floats2half2_rn(s[0] * inv, s[1] * inv);
    __half2 o1 = __floats2half2_rn(s[2] * inv, s[3] * inv);
    __half2 o2 = __floats2half2_rn(s[4] * inv, s[5] * inv);
    __half2 o3 = __floats2half2_rn(s[6] * inv, s[7] * inv);
    uint4 pk;
    pk.x = *reinterpret_cast<unsigned*>(&o0);
    pk.y = *reinterpret_cast<unsigned*>(&o1);
    pk.z = *reinterpret_cast<unsigned*>(&o2);
    pk.w = *reinterpret_cast<unsigned*>(&o3);
    *(reinterpret_cast<uint4*>(g_meanh + (size_t)node * DIM) + lane) = pk;
}

// ---------------- fp16 tensor-core GEMM (m16n8k16 mma.sync) ------------------
__device__ __forceinline__ void mma_f16(float* d, const unsigned* a, const unsigned* b) {
    asm volatile(
        "mma.sync.aligned.m16n8k16.row.col.f32.f16.f16.f32 "
        "{%0,%1,%2,%3}, {%4,%5,%6,%7}, {%8,%9}, {%0,%1,%2,%3};"
        : "+f"(d[0]), "+f"(d[1]), "+f"(d[2]), "+f"(d[3])
        : "r"(a[0]), "r"(a[1]), "r"(a[2]), "r"(a[3]),
          "r"(b[0]), "r"(b[1]));
}

// C = A0@W0^T (+ A1@W1^T) + bias; A fp16 [row][k] stride DIM, W fp16 [n][k] stride DIM.
// BM=128 BN=128 BK=16, 256 threads = 8 warps (4x2), warp tile 32x64.
#define SA 24   // smem row stride in halfs (16 + 8 pad): bank-conflict-free
template<bool RELU, bool HALF_OUT>
__global__ __launch_bounds__(256) void gemm_f16_k(
    const __half* __restrict__ A0, const __half* __restrict__ A1,
    const __half* __restrict__ W0, const __half* __restrict__ W1,
    const float* __restrict__ bias,
    __half* __restrict__ Ch, float* __restrict__ Cf,
    int Nout, int nphase)
{
    __shared__ __half As[2][128 * SA];
    __shared__ __half Ws[2][128 * SA];
    int tid = threadIdx.x;
    int lane = tid & 31, wid = tid >> 5;
    int wr = wid >> 1, wc = wid & 1;
    int i0 = blockIdx.x * 128, j0 = blockIdx.y * 128;

    int arow = tid >> 1, akb = (tid & 1) << 3;     // row / n-row, k-base (0/8)
    int gi = i0 + arow; if (gi >= NN) gi = NN - 1;
    const bool w_ok = (j0 + arow < Nout);

    float acc[2][8][4];
    #pragma unroll
    for (int mi = 0; mi < 2; ++mi)
        #pragma unroll
        for (int ni = 0; ni < 8; ++ni)
            #pragma unroll
            for (int q = 0; q < 4; ++q) acc[mi][ni][q] = 0.f;

    const int r4 = lane >> 2, c4 = lane & 3;

    for (int p = 0; p < nphase; ++p) {
        const __half* Ap = p ? A1 : A0;
        const __half* Wp = p ? W1 : W0;

        // prologue: k-tile 0 -> buf 0
        {
            uint4 ra = *reinterpret_cast<const uint4*>(Ap + (size_t)gi * DIM + akb);
            uint4 rw = make_uint4(0, 0, 0, 0);
            if (w_ok) rw = *reinterpret_cast<const uint4*>(Wp + (size_t)(j0 + arow) * DIM + akb);
            *reinterpret_cast<uint4*>(&As[0][arow * SA + akb]) = ra;
            *reinterpret_cast<uint4*>(&Ws[0][arow * SA + akb]) = rw;
        }
        __syncthreads();

        int buf = 0;
        for (int k0 = 16; k0 <= DIM; k0 += 16) {
            uint4 na, nw;
            bool have_next = (k0 < DIM);
            if (have_next) {
                na = *reinterpret_cast<const uint4*>(Ap + (size_t)gi * DIM + k0 + akb);
                nw = make_uint4(0, 0, 0, 0);
                if (w_ok) nw = *reinterpret_cast<const uint4*>(Wp + (size_t)(j0 + arow) * DIM + k0 + akb);
            }

            // compute current k16 tile
            unsigned afr[2][4];
            #pragma unroll
            for (int mi = 0; mi < 2; ++mi) {
                int row = wr * 32 + mi * 16 + r4;
                afr[mi][0] = *reinterpret_cast<const unsigned*>(&As[buf][row * SA + c4 * 2]);
                afr[mi][1] = *reinterpret_cast<const unsigned*>(&As[buf][(row + 8) * SA + c4 * 2]);
                afr[mi][2] = *reinterpret_cast<const unsigned*>(&As[buf][row * SA + c4 * 2 + 8]);
                afr[mi][3] = *reinterpret_cast<const unsigned*>(&As[buf][(row + 8) * SA + c4 * 2 + 8]);
            }
            unsigned bfr[8][2];
            #pragma unroll
            for (int ni = 0; ni < 8; ++ni) {
                int col = wc * 64 + ni * 8 + r4;
                bfr[ni][0] = *reinterpret_cast<const unsigned*>(&Ws[buf][col * SA + c4 * 2]);
                bfr[ni][1] = *reinterpret_cast<const unsigned*>(&Ws[buf][col * SA + c4 * 2 + 8]);
            }
            #pragma unroll
            for (int mi = 0; mi < 2; ++mi)
                #pragma unroll
                for (int ni = 0; ni < 8; ++ni)
                    mma_f16(acc[mi][ni], afr[mi], bfr[ni]);

            if (have_next) {
                int nb = buf ^ 1;
                *reinterpret_cast<uint4*>(&As[nb][arow * SA + akb]) = na;
                *reinterpret_cast<uint4*>(&Ws[nb][arow * SA + akb]) = nw;
                __syncthreads();
                buf = nb;
            }
        }
        __syncthreads();
    }

    // epilogue
    #pragma unroll
    for (int mi = 0; mi < 2; ++mi) {
        #pragma unroll
        for (int half = 0; half < 2; ++half) {
            int grow = i0 + wr * 32 + mi * 16 + r4 + half * 8;
            if (grow >= NN) continue;
            #pragma unroll
            for (int ni = 0; ni < 8; ++ni) {
                int gcol = j0 + wc * 64 + ni * 8 + c4 * 2;
                if (gcol >= Nout) continue;
                float v0 = acc[mi][ni][half * 2 + 0] + bias[gcol];
                float v1 = acc[mi][ni][half * 2 + 1] + bias[gcol + 1];
                if (RELU) { v0 = fmaxf(v0, 0.f); v1 = fmaxf(v1, 0.f); }
                if (HALF_OUT) {
                    __half2 hv = __floats2half2_rn(v0, v1);
                    *reinterpret_cast<__half2*>(Ch + (size_t)grow * Nout + gcol) = hv;
                } else {
                    *reinterpret_cast<float2*>(Cf + (size_t)grow * Nout + gcol) =
                        make_float2(v0, v1);
                }
            }
        }
    }
}

// ------- layer-2 tail: aggregate 40-dim + root + bias + log_softmax ----------
__global__ void agg40_lsm_k(const float* __restrict__ b2, float* __restrict__ out) {
    int node = (int)((blockIdx.x * blockDim.x + threadIdx.x) >> 5);
    if (node >= NN) return;
    int lane = threadIdx.x & 31;
    int beg = g_rowptr[node], end = g_rowptr[node + 1];
    float s0 = 0.f, s1 = 0.f;
    for (int e = beg; e < end; ++e) {
        int s = g_col[e];
        const float* zr = g_z + (size_t)s * 80;
        s0 += __ldg(zr + lane);
        if (lane < 8) s1 += __ldg(zr + 32 + lane);
    }
    float inv = g_invdeg[node];
    const float* zn = g_z + (size_t)node * 80;
    float v0 = s0 * inv + zn[40 + lane] + b2[lane];
    float v1 = (lane < 8) ? (s1 * inv + zn[72 + lane] + b2[32 + lane]) : -INFINITY;
    float m = fmaxf(v0, v1);
    #pragma unroll
    for (int off = 16; off > 0; off >>= 1)
        m = fmaxf(m, __shfl_xor_sync(0xffffffffu, m, off));
    float s = expf(v0 - m) + ((lane < 8) ? expf(v1 - m) : 0.f);
    #pragma unroll
    for (int off = 16; off > 0; off >>= 1)
        s += __shfl_xor_sync(0xffffffffu, s, off);
    float ls = m + logf(s);
    out[(size_t)node * DOUT + lane] = v0 - ls;
    if (lane < 8) out[(size_t)node * DOUT + 32 + lane] = v1 - ls;
}

// ---------------- launch -----------------------------------------------------
extern "C" void kernel_launch(void* const* d_in, const int* in_sizes, int n_in,
                              void* d_out, int out_size) {
    const float* x   = (const float*)d_in[0];
    const int*   ei  = (const int*)d_in[1];
    const int*   src = ei;
    const int*   dst = ei + NE;
    const float* Wl0 = (const float*)d_in[2];
    const float* Wr0 = (const float*)d_in[3];
    const float* b0  = (const float*)d_in[4];
    const float* Wl1 = (const float*)d_in[5];
    const float* Wr1 = (const float*)d_in[6];
    const float* b1  = (const float*)d_in[7];
    const float* Wl2 = (const float*)d_in[8];
    const float* Wr2 = (const float*)d_in[9];
    const float* b2  = (const float*)d_in[10];
    float* out = (float*)d_out;

    __half *p_xh, *p_meanh, *p_h0h, *p_h1h, *p_Wl0h, *p_Wr0h, *p_Wl1h, *p_Wr1h, *p_W2h;
    float *p_z, *p_bz;
    cudaGetSymbolAddress((void**)&p_xh, g_xh);
    cudaGetSymbolAddress((void**)&p_meanh, g_meanh);
    cudaGetSymbolAddress((void**)&p_h0h, g_h0h);
    cudaGetSymbolAddress((void**)&p_h1h, g_h1h);
    cudaGetSymbolAddress((void**)&p_Wl0h, g_Wl0h);
    cudaGetSymbolAddress((void**)&p_Wr0h, g_Wr0h);
    cudaGetSymbolAddress((void**)&p_Wl1h, g_Wl1h);
    cudaGetSymbolAddress((void**)&p_Wr1h, g_Wr1h);
    cudaGetSymbolAddress((void**)&p_W2h, g_W2h);
    cudaGetSymbolAddress((void**)&p_z, g_z);
    cudaGetSymbolAddress((void**)&p_bz, g_bzero);

    // CSR build + conversions
    zero_deg_k<<<(NN + 255) / 256, 256>>>();
    count_deg_k<<<(NE + 255) / 256, 256>>>(dst);
    scan_k<<<1, 1024>>>();
    fill_csr_k<<<(NE + 255) / 256, 256>>>(src, dst);
    conv_x_k<<<(NN * DIM / 4 + 255) / 256, 256>>>(x);
    wpack_k<<<(DIM * DIM + 255) / 256, 256>>>(Wl0, p_Wl0h, DIM);
    wpack_k<<<(DIM * DIM + 255) / 256, 256>>>(Wr0, p_Wr0h, DIM);
    wpack_k<<<(DIM * DIM + 255) / 256, 256>>>(Wl1, p_Wl1h, DIM);
    wpack_k<<<(DIM * DIM + 255) / 256, 256>>>(Wr1, p_Wr1h, DIM);
    wpack_k<<<(DOUT * DIM + 255) / 256, 256>>>(Wl2, p_W2h, DOUT);
    wpack_k<<<(DOUT * DIM + 255) / 256, 256>>>(Wr2, p_W2h + (size_t)DOUT * DIM, DOUT);

    dim3 gmain((NN + 127) / 128, 2);   // Nout=256
    dim3 gz((NN + 127) / 128, 1);      // Nout=80
    int aggBlocks = (NN * 32 + 255) / 256;

    // layer 0
    aggregate_h_k<<<aggBlocks, 256>>>(p_xh);
    gemm_f16_k<true, true><<<gmain, 256>>>(p_meanh, p_xh, p_Wl0h, p_Wr0h, b0,
                                           p_h0h, nullptr, DIM, 2);
    // layer 1
    aggregate_h_k<<<aggBlocks, 256>>>(p_h0h);
    gemm_f16_k<true, true><<<gmain, 256>>>(p_meanh, p_h0h, p_Wl1h, p_Wr1h, b1,
                                           p_h1h, nullptr, DIM, 2);
    // layer 2: project to 80-dim first (linearity), then aggregate + softmax
    gemm_f16_k<false, false><<<gz, 256>>>(p_h1h, nullptr, p_W2h, nullptr, p_bz,
                                          nullptr, p_z, 80, 1);
    agg40_lsm_k<<<aggBlocks, 256>>>(b2, out);
}